// round 4
// baseline (speedup 1.0000x reference)
#include <cuda_runtime.h>
#include <cuda_bf16.h>

#define T_STEPS 512
#define BATCH   64
#define NIN     1024
#define HDIM    1024
#define G4      4096      // 4*H
#define GRID_R  128       // persistent blocks (<= 148 SMs -> co-resident)
#define THR_R   128
#define HPB     8         // h-columns per block (8*4 gates = 32 gate cols)
#define KC      128       // y k-chunk
#define YS_STRIDE 132     // padded row stride for y smem

// -------- scratch (device globals: allocation-free rule) --------
__device__ float    g_zx[134217728];          // 32768 x 4096 fp32 (512 MB)
__device__ float    g_ybuf[2][BATCH * HDIM];  // double-buffered y state
__device__ unsigned g_bar;

__global__ void init_bar_kernel() { g_bar = 0u; }

// ================= Kernel 1: Zx = X @ Wx + b =================
// M=32768, N=4096, K=1024. BM=128, BN=64, BK=16, 256 threads, 8x4/thread.
__global__ __launch_bounds__(256) void zx_gemm_kernel(
    const float* __restrict__ X, const float* __restrict__ W,
    const float* __restrict__ bias)
{
    __shared__ float As[16][128];   // [k][m] (transposed for vector reads)
    __shared__ float Bs[16][64];    // [k][n]

    const int bm = blockIdx.y * 128;
    const int bn = blockIdx.x * 64;
    const int tid = threadIdx.x;
    const int tx = tid & 15;          // n-group (4 cols)
    const int ty = tid >> 4;          // m-group (8 rows)
    const int ar = tid >> 2;          // A load row (0..63)
    const int ac = (tid & 3) << 2;    // A load k   (0,4,8,12)
    const int br = tid >> 4;          // B load row (0..15)
    const int bc = (tid & 15) << 2;   // B load col (0..60)

    float acc[8][4];
#pragma unroll
    for (int i = 0; i < 8; i++)
#pragma unroll
        for (int j = 0; j < 4; j++) acc[i][j] = 0.0f;

    for (int k0 = 0; k0 < NIN; k0 += 16) {
        float4 a0 = *(const float4*)&X[(size_t)(bm + ar) * NIN + k0 + ac];
        float4 a1 = *(const float4*)&X[(size_t)(bm + ar + 64) * NIN + k0 + ac];
        float4 b0 = *(const float4*)&W[(size_t)(k0 + br) * G4 + bn + bc];
        __syncthreads();
        As[ac + 0][ar] = a0.x; As[ac + 1][ar] = a0.y;
        As[ac + 2][ar] = a0.z; As[ac + 3][ar] = a0.w;
        As[ac + 0][ar + 64] = a1.x; As[ac + 1][ar + 64] = a1.y;
        As[ac + 2][ar + 64] = a1.z; As[ac + 3][ar + 64] = a1.w;
        *(float4*)&Bs[br][bc] = b0;
        __syncthreads();
#pragma unroll
        for (int kk = 0; kk < 16; kk++) {
            float av[8], bv[4];
            *(float4*)&av[0] = *(const float4*)&As[kk][ty * 8];
            *(float4*)&av[4] = *(const float4*)&As[kk][ty * 8 + 4];
            *(float4*)&bv[0] = *(const float4*)&Bs[kk][tx * 4];
#pragma unroll
            for (int i = 0; i < 8; i++)
#pragma unroll
                for (int j = 0; j < 4; j++)
                    acc[i][j] = fmaf(av[i], bv[j], acc[i][j]);
        }
    }

    float4 bb = *(const float4*)&bias[bn + tx * 4];
#pragma unroll
    for (int i = 0; i < 8; i++) {
        float4 o;
        o.x = acc[i][0] + bb.x; o.y = acc[i][1] + bb.y;
        o.z = acc[i][2] + bb.z; o.w = acc[i][3] + bb.w;
        *(float4*)&g_zx[(size_t)(bm + ty * 8 + i) * G4 + bn + tx * 4] = o;
    }
}

// ================= Kernel 2: persistent recurrence =================
// smem layout (floats):
//   whs : [0, 32768)                      Wh slice [k][32]
//   ys  : [32768, 32768+2*8448)           double-buffered y chunks [64][132]
//   zs  : [49664, 49664+2048)             z exchange [64][32]
//   cs  : [51712, 51712+512)              c state [64][8]
#define SM_YS 32768
#define SM_ZS (32768 + 2 * (BATCH * YS_STRIDE))
#define SM_CS (SM_ZS + BATCH * 32)
#define SMEM_FLOATS (SM_CS + BATCH * HPB)
#define SMEM_BYTES (SMEM_FLOATS * 4)

__device__ __forceinline__ void cp16(unsigned saddr, const void* gptr) {
    asm volatile("cp.async.cg.shared.global [%0], [%1], 16;\n" :: "r"(saddr), "l"(gptr));
}
__device__ __forceinline__ void cp_commit() { asm volatile("cp.async.commit_group;\n"); }
__device__ __forceinline__ void cp_wait0()  { asm volatile("cp.async.wait_group 0;\n" ::: "memory"); }

__device__ __forceinline__ float sigf(float x) { return 0.5f * tanhf(0.5f * x) + 0.5f; }

__device__ __forceinline__ void load_y_chunk(int tid, float* dst, const float* src) {
    // copy 64 x 128 floats (32 KB) as 2048 16B groups; .cg bypasses L1 (no staleness)
#pragma unroll
    for (int g = 0; g < 16; g++) {
        int grp = tid + g * THR_R;       // 0..2047
        int b = grp >> 5, q = grp & 31;  // b: batch, q: 16B unit (4 floats)
        unsigned sa = (unsigned)__cvta_generic_to_shared(dst + b * YS_STRIDE + q * 4);
        cp16(sa, src + b * HDIM + q * 4);
    }
    cp_commit();
}

__global__ __launch_bounds__(THR_R, 1) void lstm_kernel(
    const float* __restrict__ W,      // (2048, 4096); Wh = rows [1024, 2048)
    const float* __restrict__ y0,
    const float* __restrict__ c0,
    const float* __restrict__ Igate,  // (T, B)
    float* __restrict__ out)
{
    extern __shared__ float smem[];
    float* whs = smem;
    float* ys  = smem + SM_YS;
    float* zs  = smem + SM_ZS;
    float* cs  = smem + SM_CS;

    const int tid = threadIdx.x;
    const int blk = blockIdx.x;
    const int cg  = tid & 7;    // col group: local gate-cols 4cg..4cg+3
    const int bg  = tid >> 3;   // batch group: batches 4bg..4bg+3
    // local col c=4cg+i maps to global gate col: gate=(c>>3), jj=(c&7)
    const int gqbase = (cg >> 1) * HDIM + blk * HPB + (cg & 1) * 4;

    // ---- one-time: Wh slice -> smem, c0 -> smem ----
    const float* WhG = W + (size_t)NIN * G4;
    for (int idx = tid; idx < NIN * 32; idx += THR_R) {
        int k = idx >> 5, c = idx & 31;
        int gq = (c >> 3) * HDIM + blk * HPB + (c & 7);
        whs[k * 32 + c] = WhG[(size_t)k * G4 + gq];
    }
    for (int p = tid; p < BATCH * HPB; p += THR_R)
        cs[p] = c0[(p >> 3) * HDIM + blk * HPB + (p & 7)];
    __syncthreads();

    float* Yout  = out;
    float* Cout  = out + (size_t)T_STEPS * BATCH * HDIM;
    float* cTout = Cout + (size_t)T_STEPS * BATCH * HDIM;

    for (int t = 0; t < T_STEPS; t++) {
        const float* ysrc = (t == 0) ? y0 : g_ybuf[(t & 1) ^ 1];

        // init accumulators from Zx[t] (+bias already folded in)
        float acc[4][4];
#pragma unroll
        for (int j = 0; j < 4; j++) {
            float4 z4 = *(const float4*)&g_zx[((size_t)t * BATCH + (bg * 4 + j)) * G4 + gqbase];
            acc[j][0] = z4.x; acc[j][1] = z4.y; acc[j][2] = z4.z; acc[j][3] = z4.w;
        }

        // prefetch chunk 0
        load_y_chunk(tid, ys, ysrc);
        cp_wait0();
        __syncthreads();

        // ---- z_slice += y_prev @ Wh_slice, chunked over k ----
        for (int ch = 0; ch < HDIM / KC; ch++) {
            if (ch < HDIM / KC - 1)
                load_y_chunk(tid, ys + ((ch + 1) & 1) * (BATCH * YS_STRIDE),
                             ysrc + (ch + 1) * KC);

            const float* yb = ys + (ch & 1) * (BATCH * YS_STRIDE) + (bg * 4) * YS_STRIDE;
            const float* wb = whs + (ch * KC) * 32 + (cg << 2);
#pragma unroll 4
            for (int kl4 = 0; kl4 < KC / 4; kl4++) {
                float4 wv[4];
                wv[0] = *(const float4*)(wb + (kl4 * 4 + 0) * 32);
                wv[1] = *(const float4*)(wb + (kl4 * 4 + 1) * 32);
                wv[2] = *(const float4*)(wb + (kl4 * 4 + 2) * 32);
                wv[3] = *(const float4*)(wb + (kl4 * 4 + 3) * 32);
#pragma unroll
                for (int j = 0; j < 4; j++) {
                    float4 yv = *(const float4*)(yb + j * YS_STRIDE + kl4 * 4);
                    float yy[4] = {yv.x, yv.y, yv.z, yv.w};
#pragma unroll
                    for (int kk = 0; kk < 4; kk++) {
                        acc[j][0] = fmaf(yy[kk], wv[kk].x, acc[j][0]);
                        acc[j][1] = fmaf(yy[kk], wv[kk].y, acc[j][1]);
                        acc[j][2] = fmaf(yy[kk], wv[kk].z, acc[j][2]);
                        acc[j][3] = fmaf(yy[kk], wv[kk].w, acc[j][3]);
                    }
                }
            }
            if (ch < HDIM / KC - 1) cp_wait0();
            __syncthreads();
        }

        // ---- exchange z through smem (gates live in different threads) ----
#pragma unroll
        for (int j = 0; j < 4; j++)
            *(float4*)&zs[(bg * 4 + j) * 32 + (cg << 2)] =
                make_float4(acc[j][0], acc[j][1], acc[j][2], acc[j][3]);
        __syncthreads();

        // ---- elementwise LSTM cell: 512 (b,jj) pairs, 4 per thread ----
        float* ywr = g_ybuf[t & 1];
#pragma unroll
        for (int q = 0; q < 4; q++) {
            int p = tid + q * THR_R;
            int b = p >> 3, jj = p & 7;
            float z0 = zs[b * 32 + jj];          // cell input
            float z1 = zs[b * 32 + 8 + jj];      // input gate
            float z2 = zs[b * 32 + 16 + jj];     // forget gate
            float z3 = zs[b * 32 + 24 + jj];     // output gate
            float ci = tanhf(z0);
            float ig = sigf(z1);
            float fg = sigf(z2);
            float og = sigf(z3);
            float cprev = cs[p];
            float c = fmaf(ci, ig, cprev * fg);
            float y = tanhf(c) * og;
            float m = Igate[t * BATCH + b];
            c = m * c + (1.0f - m) * cprev;
            y = m * y;
            cs[p] = c;
            size_t row = (size_t)t * BATCH + b;
            int h = blk * HPB + jj;
            Yout[row * HDIM + h] = y;
            Cout[row * HDIM + h] = c;
            ywr[b * HDIM + h]    = y;
        }

        // ---- grid barrier (release: fence-all + sync + one atomic) ----
        __threadfence();
        __syncthreads();
        if (tid == 0) {
            atomicAdd(&g_bar, 1u);
            unsigned target = (unsigned)GRID_R * (unsigned)(t + 1);
            const volatile unsigned* vb = (const volatile unsigned*)&g_bar;
            while (*vb < target) { }
            __threadfence();  // acquire
        }
        __syncthreads();
    }

    // final cell state
#pragma unroll
    for (int q = 0; q < 4; q++) {
        int p = tid + q * THR_R;
        cTout[(p >> 3) * HDIM + blk * HPB + (p & 7)] = cs[p];
    }
}

// ================= host =================
extern "C" void kernel_launch(void* const* d_in, const int* in_sizes, int n_in,
                              void* d_out, int out_size)
{
    (void)in_sizes; (void)n_in; (void)out_size;
    const float* X    = (const float*)d_in[0];
    const float* W    = (const float*)d_in[1];
    const float* bias = (const float*)d_in[2];
    const float* y0   = (const float*)d_in[3];
    const float* c0   = (const float*)d_in[4];
    const float* I    = (const float*)d_in[5];
    float* out = (float*)d_out;

    cudaFuncSetAttribute(lstm_kernel,
                         cudaFuncAttributeMaxDynamicSharedMemorySize, SMEM_BYTES);

    init_bar_kernel<<<1, 1>>>();

    dim3 g1(G4 / 64, (T_STEPS * BATCH) / 128);
    zx_gemm_kernel<<<g1, 256>>>(X, W, bias);

    lstm_kernel<<<GRID_R, THR_R, SMEM_BYTES>>>(W, y0, c0, I, out);
}

// round 5
// speedup vs baseline: 2.3103x; 2.3103x over previous
#include <cuda_runtime.h>
#include <cuda_bf16.h>
#include <cstdint>

#define T_STEPS 512
#define BATCH   64
#define NIN     1024
#define HDIM    1024
#define G4      4096      // 4*H
#define GRID_R  128       // persistent blocks (<= 148 SMs -> co-resident)
#define THR_R   128
#define HPB     8         // h-columns per block (8*4 gates = 32 gate cols)
#define KC      128       // y k-chunk
#define YS_STRIDE 132     // padded row stride for y smem

// -------- scratch (device globals: allocation-free rule) --------
__device__ float    g_zx[134217728];          // 32768 x 4096 fp32 (512 MB)
__device__ float    g_ybuf[2][BATCH * HDIM];  // double-buffered y state (tf32-rounded)
__device__ unsigned g_bar;

__global__ void init_bar_kernel() { g_bar = 0u; }

// ---------------- small helpers ----------------
__device__ __forceinline__ void cp16(unsigned saddr, const void* gptr) {
    asm volatile("cp.async.cg.shared.global [%0], [%1], 16;\n" :: "r"(saddr), "l"(gptr));
}
__device__ __forceinline__ void cp_commit() { asm volatile("cp.async.commit_group;\n"); }
__device__ __forceinline__ void cp_wait0()  { asm volatile("cp.async.wait_group 0;\n" ::: "memory"); }

__device__ __forceinline__ float sigf(float x) { return 0.5f * tanhf(0.5f * x) + 0.5f; }

__device__ __forceinline__ uint32_t tf32b(float x) {
    uint32_t u; asm("cvt.rna.tf32.f32 %0, %1;" : "=r"(u) : "f"(x)); return u;
}
__device__ __forceinline__ float tf32r(float x) {
    return __uint_as_float(tf32b(x));
}
__device__ __forceinline__ void mma_tf32(float* d, const uint32_t* a, const uint32_t* b) {
    asm volatile(
        "mma.sync.aligned.m16n8k8.row.col.f32.tf32.tf32.f32 "
        "{%0,%1,%2,%3}, {%4,%5,%6,%7}, {%8,%9}, {%0,%1,%2,%3};"
        : "+f"(d[0]), "+f"(d[1]), "+f"(d[2]), "+f"(d[3])
        : "r"(a[0]), "r"(a[1]), "r"(a[2]), "r"(a[3]), "r"(b[0]), "r"(b[1]));
}
__device__ __forceinline__ void ldsm4(uint32_t* r, const float* p) {
    uint32_t sa = (uint32_t)__cvta_generic_to_shared(p);
    asm volatile("ldmatrix.sync.aligned.m8n8.x4.shared.b16 {%0,%1,%2,%3}, [%4];"
                 : "=r"(r[0]), "=r"(r[1]), "=r"(r[2]), "=r"(r[3]) : "r"(sa));
}

// ================= Kernel 1: Zx = X @ Wx + b (TF32 mma) =================
// M=32768, N=4096, K=1024. BM=128, BN=128, BK=16, 256 thr (8 warps 2x4),
// warp tile 64x32 (4 m-tiles x 4 n-tiles of m16n8k8).
#define ZA_STRIDE 20     // floats per A smem row (80B, 16B-aligned, conflict-free ldsm)
#define ZB_STRIDE 132    // floats per B smem row

__global__ __launch_bounds__(256) void zx_gemm_kernel(
    const float* __restrict__ X, const float* __restrict__ W,
    const float* __restrict__ bias)
{
    __shared__ __align__(16) float As[2][128 * ZA_STRIDE];
    __shared__ __align__(16) float Bs[2][16 * ZB_STRIDE];

    const int bm = blockIdx.y * 128;
    const int bn = blockIdx.x * 128;
    const int tid = threadIdx.x;
    const int wid = tid >> 5, lane = tid & 31;
    const int wm = (wid & 1) * 64;      // warp m offset
    const int wn = (wid >> 1) * 32;     // warp n offset
    const int g = lane >> 2, tg = lane & 3;
    // ldmatrix per-lane addressing pieces
    const int t4 = lane >> 3, lr = lane & 7;
    const int rowb = wm + 8 * (t4 & 1) + lr;  // + mt*16
    const int kadd = 4 * (t4 >> 1);           // + kt*8

    float acc[4][4][4];
#pragma unroll
    for (int a = 0; a < 4; a++)
#pragma unroll
        for (int b = 0; b < 4; b++)
#pragma unroll
            for (int i = 0; i < 4; i++) acc[a][b][i] = 0.0f;

    // tile loader: 512 16B units for A, 512 for B; 2 each per thread
    auto load_tiles = [&](int buf, int k0) {
#pragma unroll
        for (int h = 0; h < 2; h++) {
            int u = tid + h * 256;
            int row = u >> 2, q = u & 3;
            cp16((unsigned)__cvta_generic_to_shared(&As[buf][row * ZA_STRIDE + q * 4]),
                 X + (size_t)(bm + row) * NIN + k0 + q * 4);
            int k = u >> 5, qq = u & 31;
            cp16((unsigned)__cvta_generic_to_shared(&Bs[buf][k * ZB_STRIDE + qq * 4]),
                 W + (size_t)(k0 + k) * G4 + bn + qq * 4);
        }
        cp_commit();
    };

    load_tiles(0, 0);

    for (int kb = 0; kb < NIN / 16; kb++) {
        const int cur = kb & 1;
        cp_wait0();
        __syncthreads();
        if (kb < NIN / 16 - 1) load_tiles(cur ^ 1, (kb + 1) * 16);

        const float* A_ = As[cur];
        const float* B_ = Bs[cur];
#pragma unroll
        for (int kt = 0; kt < 2; kt++) {
            uint32_t a[4][4];
#pragma unroll
            for (int mt = 0; mt < 4; mt++) {
                ldsm4(a[mt], &A_[(rowb + mt * 16) * ZA_STRIDE + kt * 8 + kadd]);
#pragma unroll
                for (int j = 0; j < 4; j++)
                    a[mt][j] = tf32b(__uint_as_float(a[mt][j]));
            }
            uint32_t b[4][2];
#pragma unroll
            for (int nt = 0; nt < 4; nt++) {
                b[nt][0] = tf32b(B_[(kt * 8 + tg) * ZB_STRIDE + wn + nt * 8 + g]);
                b[nt][1] = tf32b(B_[(kt * 8 + tg + 4) * ZB_STRIDE + wn + nt * 8 + g]);
            }
#pragma unroll
            for (int mt = 0; mt < 4; mt++)
#pragma unroll
                for (int nt = 0; nt < 4; nt++)
                    mma_tf32(acc[mt][nt], a[mt], b[nt]);
        }
        __syncthreads();
    }

    // epilogue: add bias, store fp32
#pragma unroll
    for (int mt = 0; mt < 4; mt++) {
#pragma unroll
        for (int nt = 0; nt < 4; nt++) {
            int n = bn + wn + nt * 8 + 2 * tg;
            float2 bb = *(const float2*)&bias[n];
            int m0 = bm + wm + mt * 16 + g;
            float2 v0 = make_float2(acc[mt][nt][0] + bb.x, acc[mt][nt][1] + bb.y);
            float2 v1 = make_float2(acc[mt][nt][2] + bb.x, acc[mt][nt][3] + bb.y);
            *(float2*)&g_zx[(size_t)m0 * G4 + n] = v0;
            *(float2*)&g_zx[(size_t)(m0 + 8) * G4 + n] = v1;
        }
    }
}

// ================= Kernel 2: persistent recurrence (TF32 mma) =================
// Per block: z^T tile M=32 (gate cols) x N=64 (batch), K=1024.
// whsF: Wh^T pre-converted to tf32 in mma-fragment layout:
//   whsF[((kt*2+mt)*32 + lane)*4 + i] = a_i fragment value.
// smem floats:
#define SM_YS 32768
#define SM_ZS (32768 + 2 * (BATCH * YS_STRIDE))
#define SM_CS (SM_ZS + BATCH * 32)
#define SMEM_FLOATS (SM_CS + BATCH * HPB)
#define SMEM_BYTES (SMEM_FLOATS * 4)

__device__ __forceinline__ void load_y_chunk(int tid, float* dst, const float* src) {
#pragma unroll
    for (int gq = 0; gq < 16; gq++) {
        int grp = tid + gq * THR_R;       // 0..2047
        int b = grp >> 5, q = grp & 31;
        unsigned sa = (unsigned)__cvta_generic_to_shared(dst + b * YS_STRIDE + q * 4);
        cp16(sa, src + b * HDIM + q * 4);
    }
    cp_commit();
}

__device__ __forceinline__ void grid_bar(int tid, unsigned target) {
    __threadfence();
    __syncthreads();
    if (tid == 0) {
        atomicAdd(&g_bar, 1u);
        volatile unsigned* vb = &g_bar;
        while (*vb < target) { }
        __threadfence();
    }
    __syncthreads();
}

__global__ __launch_bounds__(THR_R, 1) void lstm_kernel(
    const float* __restrict__ W,      // (2048, 4096); Wh = rows [1024, 2048)
    const float* __restrict__ y0,
    const float* __restrict__ c0,
    const float* __restrict__ Igate,  // (T, B)
    float* __restrict__ out)
{
    extern __shared__ float smem[];
    float* whs = smem;            // 32768 floats: fragment-layout tf32 Wh^T
    float* ys  = smem + SM_YS;    // double-buffered y chunks
    float* zs  = smem + SM_ZS;    // z exchange [64][32]
    float* cs  = smem + SM_CS;    // c state [64][8]

    const int tid = threadIdx.x;
    const int blk = blockIdx.x;
    const int w = tid >> 5, lane = tid & 31;
    const int g = lane >> 2, tg = lane & 3;

    // ---- one-time: Wh^T fragment layout (tf32-rounded) ----
    const float* WhG = W + (size_t)NIN * G4;
    for (int idx = tid; idx < NIN * 32; idx += THR_R) {
        int i = idx & 3;
        int ln = (idx >> 2) & 31;
        int mt = (idx >> 7) & 1;
        int kt = idx >> 8;                       // 0..127
        int gg = ln >> 2, tg2 = ln & 3;
        int k = 8 * kt + tg2 + 4 * (i >> 1);
        int gcol = (2 * mt + (i & 1)) * HDIM + blk * HPB + gg;
        whs[idx] = tf32r(WhG[(size_t)k * G4 + gcol]);
    }
    for (int p = tid; p < BATCH * HPB; p += THR_R)
        cs[p] = c0[(p >> 3) * HDIM + blk * HPB + (p & 7)];

    // ---- pre-round y0 into g_ybuf[1] (the t=0 source), grid-partitioned ----
    for (int p = blk * THR_R + tid; p < BATCH * HDIM; p += GRID_R * THR_R)
        g_ybuf[1][p] = tf32r(y0[p]);
    grid_bar(tid, GRID_R);   // phase 0

    float* Yout  = out;
    float* Cout  = out + (size_t)T_STEPS * BATCH * HDIM;
    float* cTout = Cout + (size_t)T_STEPS * BATCH * HDIM;

    for (int t = 0; t < T_STEPS; t++) {
        const float* ysrc = g_ybuf[(t & 1) ^ 1];

        // prefetch Zx values for epilogue (consumed at step end; latency hidden)
        float zxr[2][2][4];
        {
            size_t trow = (size_t)t * BATCH;
#pragma unroll
            for (int mt = 0; mt < 2; mt++)
#pragma unroll
                for (int h = 0; h < 2; h++) {
                    int gcol = (2 * mt + h) * HDIM + blk * HPB + g;
#pragma unroll
                    for (int nt = 0; nt < 2; nt++)
#pragma unroll
                        for (int j = 0; j < 2; j++) {
                            int b = 16 * w + 8 * nt + 2 * tg + j;
                            zxr[mt][nt][2 * h + j] =
                                __ldg(&g_zx[(trow + b) * G4 + gcol]);
                        }
                }
        }

        float acc[2][2][4];
#pragma unroll
        for (int a = 0; a < 2; a++)
#pragma unroll
            for (int b = 0; b < 2; b++)
#pragma unroll
                for (int i = 0; i < 4; i++) acc[a][b][i] = 0.0f;

        // prefetch y chunk 0
        load_y_chunk(tid, ys, ysrc);
        cp_wait0();
        __syncthreads();

        // ---- z^T += Wh^T @ y^T, chunked over k ----
        for (int ch = 0; ch < HDIM / KC; ch++) {
            if (ch < HDIM / KC - 1)
                load_y_chunk(tid, ys + ((ch + 1) & 1) * (BATCH * YS_STRIDE),
                             ysrc + (ch + 1) * KC);

            const float* yb = ys + (ch & 1) * (BATCH * YS_STRIDE);
#pragma unroll
            for (int ktl = 0; ktl < 16; ktl++) {
                int ktg = ch * 16 + ktl;
                const float4* wp = ((const float4*)whs) + (size_t)(ktg * 2) * 32 + lane;
                float4 A0 = wp[0];
                float4 A1 = wp[32];
                uint32_t a0[4] = {__float_as_uint(A0.x), __float_as_uint(A0.y),
                                  __float_as_uint(A0.z), __float_as_uint(A0.w)};
                uint32_t a1[4] = {__float_as_uint(A1.x), __float_as_uint(A1.y),
                                  __float_as_uint(A1.z), __float_as_uint(A1.w)};
                int krow = ktl * 8 + tg;
                uint32_t b0[2], b1[2];
                b0[0] = __float_as_uint(yb[(16 * w + g) * YS_STRIDE + krow]);
                b0[1] = __float_as_uint(yb[(16 * w + g) * YS_STRIDE + krow + 4]);
                b1[0] = __float_as_uint(yb[(16 * w + 8 + g) * YS_STRIDE + krow]);
                b1[1] = __float_as_uint(yb[(16 * w + 8 + g) * YS_STRIDE + krow + 4]);
                mma_tf32(acc[0][0], a0, b0);
                mma_tf32(acc[0][1], a0, b1);
                mma_tf32(acc[1][0], a1, b0);
                mma_tf32(acc[1][1], a1, b1);
            }
            if (ch < HDIM / KC - 1) cp_wait0();
            __syncthreads();
        }

        // ---- epilogue: z = acc + zx into zs[b][m] ----
#pragma unroll
        for (int mt = 0; mt < 2; mt++)
#pragma unroll
            for (int nt = 0; nt < 2; nt++)
#pragma unroll
                for (int h = 0; h < 2; h++)
#pragma unroll
                    for (int j = 0; j < 2; j++) {
                        int m = 16 * mt + 8 * h + g;
                        int b = 16 * w + 8 * nt + 2 * tg + j;
                        zs[b * 32 + m] = acc[mt][nt][2 * h + j] + zxr[mt][nt][2 * h + j];
                    }
        __syncthreads();

        // ---- elementwise LSTM cell: 512 (b,jj) pairs, 4 per thread ----
        float* ywr = g_ybuf[t & 1];
#pragma unroll
        for (int q = 0; q < 4; q++) {
            int p = tid + q * THR_R;
            int b = p >> 3, jj = p & 7;
            float z0 = zs[b * 32 + jj];          // cell input
            float z1 = zs[b * 32 + 8 + jj];      // input gate
            float z2 = zs[b * 32 + 16 + jj];     // forget gate
            float z3 = zs[b * 32 + 24 + jj];     // output gate
            float ci = tanhf(z0);
            float ig = sigf(z1);
            float fg = sigf(z2);
            float og = sigf(z3);
            float cprev = cs[p];
            float c = fmaf(ci, ig, cprev * fg);
            float y = tanhf(c) * og;
            float m = Igate[t * BATCH + b];
            c = m * c + (1.0f - m) * cprev;
            y = m * y;
            cs[p] = c;
            size_t row = (size_t)t * BATCH + b;
            int hcol = blk * HPB + jj;
            Yout[row * HDIM + hcol] = y;
            Cout[row * HDIM + hcol] = c;
            ywr[b * HDIM + hcol]    = tf32r(y);   // rounded copy feeds next-step mma
        }

        grid_bar(tid, (unsigned)GRID_R * (unsigned)(t + 2));
    }

    // final cell state
#pragma unroll
    for (int q = 0; q < 4; q++) {
        int p = tid + q * THR_R;
        cTout[(p >> 3) * HDIM + blk * HPB + (p & 7)] = cs[p];
    }
}

// ================= host =================
extern "C" void kernel_launch(void* const* d_in, const int* in_sizes, int n_in,
                              void* d_out, int out_size)
{
    (void)in_sizes; (void)n_in; (void)out_size;
    const float* X    = (const float*)d_in[0];
    const float* W    = (const float*)d_in[1];
    const float* bias = (const float*)d_in[2];
    const float* y0   = (const float*)d_in[3];
    const float* c0   = (const float*)d_in[4];
    const float* I    = (const float*)d_in[5];
    float* out = (float*)d_out;

    cudaFuncSetAttribute(lstm_kernel,
                         cudaFuncAttributeMaxDynamicSharedMemorySize, SMEM_BYTES);

    init_bar_kernel<<<1, 1>>>();

    dim3 g1(G4 / 128, (T_STEPS * BATCH) / 128);
    zx_gemm_kernel<<<g1, 256>>>(X, W, bias);

    lstm_kernel<<<GRID_R, THR_R, SMEM_BYTES>>>(W, y0, c0, I, out);
}